// round 15
// baseline (speedup 1.0000x reference)
#include <cuda_runtime.h>

// ---------------- problem constants ----------------
#define NZ     300
#define NX     400
#define NPML   32
#define NZP    (NZ + 2*NPML)            // 364
#define NXP    (NX + 2*NPML)            // 464
#define NXPP   480                      // global row pitch (floats)
#define NSTEPS 200
#define NSHOTS 2
#define DXC    0.01f
#define DTC    0.001f
#define SRC_Z  (NPML + 2)               // 34
#define REC_Z  (NPML + 2)               // 34

#define FSZ (NZP * NXPP)

#define BLKS_PER_SHOT 74
#define NBLK   (NSHOTS * BLKS_PER_SHOT) // 148
#define NTHR   1024
#define NCMP   960                      // compute threads (warps 0-29)
#define MAXC   3                        // 960*3 = 2880 >= 2320 max cells

// smem tile: row r <-> global row z0-2+r
//   r=0 guard(0), r=1 = z0-1 (vx/vz imported, sxz recomputed),
//   r=2..nrows+1 owned, r=nrows+2 = z1 (vx/vz imported, szz recomputed)
#define SROWS  8
#define SPITCH 480
#define FTILE  (SROWS * SPITCH)
#define SMEM_DYN (5 * FTILE * 4)        // 76800 B

// enc = soff | flags<<20
#define F_VAL  1
#define F_REC  2
#define F_SRC  4
#define F_TOP  8     // r == 2        -> publish vx,vz to lo
#define F_BOT  16    // r == nrows+1  -> publish vx,vz to hi

// ---------------- device state (static, no allocs) ----------------
// parity double-buffered velocity exchange: writer of step t uses [t&1];
// reader of step t reads [t&1]. Overrun-proof (see proof in header comment).
__device__ float g_vx[2][NSHOTS][FSZ];
__device__ float g_vz[2][NSHOTS][FSZ];

__device__ unsigned g_flags[NBLK * 32];   // monotonic, 128B apart
__device__ double   g_part[NBLK];
__device__ unsigned g_done = 0u;

__device__ __forceinline__ void st_release_u32(unsigned* p, unsigned v)
{
    asm volatile("st.release.gpu.global.u32 [%0], %1;" :: "l"(p), "r"(v) : "memory");
}
__device__ __forceinline__ unsigned ld_acquire_u32(const unsigned* p)
{
    unsigned v;
    asm volatile("ld.acquire.gpu.global.u32 %0, [%1];" : "=r"(v) : "l"(p) : "memory");
    return v;
}
__device__ __forceinline__ void wait_flag(const unsigned* f, unsigned q)
{
    while ((int)(ld_acquire_u32(f) - q) < 0) { }
}

__global__ void __launch_bounds__(NTHR, 1)
fwi_persistent(const float* __restrict__ Vp,
               const float* __restrict__ Vs,
               const float* __restrict__ Den,
               const float* __restrict__ Stf,
               const float* __restrict__ Mask,
               const int*   __restrict__ ShotIds,
               float*       __restrict__ out)
{
    extern __shared__ float sm[];
    float* __restrict__ s_vx  = sm;
    float* __restrict__ s_vz  = sm + 1 * FTILE;
    float* __restrict__ s_sxx = sm + 2 * FTILE;
    float* __restrict__ s_szz = sm + 3 * FTILE;
    float* __restrict__ s_sxz = sm + 4 * FTILE;

    const int b   = blockIdx.x;
    const int s   = b / BLKS_PER_SHOT;
    const int kk  = b - s * BLKS_PER_SHOT;
    const int z0  = (kk * NZP) / BLKS_PER_SHOT;
    const int z1  = ((kk + 1) * NZP) / BLKS_PER_SHOT;
    const int nrows  = z1 - z0;
    const int ncells = nrows * NXP;
    const int tid = threadIdx.x;
    const int wid = tid >> 5;
    const int lane = tid & 31;

    const int nb_lo = (kk > 0)                 ? b - 1 : -1;
    const int nb_hi = (kk < BLKS_PER_SHOT - 1) ? b + 1 : -1;

    const int gbase = (z0 - 2) * NXPP;     // global offset of smem row 0

    unsigned  q      = *(volatile unsigned*)&g_flags[b * 32];   // replay-safe base
    unsigned* myflag = &g_flags[b * 32];

    // roles
    const bool isComp   = (wid < 30);
    const bool isTopImp = (wid == 30) && (nb_lo >= 0);
    const bool isBotImp = (wid == 31) && (nb_hi >= 0);

    // ---------- zero smem tiles ----------
    for (int c = tid; c < 5 * FTILE; c += NTHR) sm[c] = 0.0f;

    // ---------- coefficient helper (A = dt*(lam+2mu)/dx, C = dt*mu/dx) ----------
    auto coef = [&](int i, int j, float& dtr, float& dmp, float& a, float& cc) {
        int ip = min(max(i - NPML, 0), NZ - 1);
        int jp = min(max(j - NPML, 0), NX - 1);
        float vp  = Vp [ip * NX + jp];
        float vs  = Vs [ip * NX + jp];
        float den = Den[ip * NX + jp];
        float m   = Mask[i * NXP + j];
        vp  = m * vp  + (1.0f - m) * vp;
        vs  = m * vs  + (1.0f - m) * vs;
        den = m * den + (1.0f - m) * den;
        float mu  = vs * vs * den * 1e-6f;
        float lam = (vp * vp - 2.0f * vs * vs) * den * 1e-6f;
        const float inv_dx = 1.0f / DXC;
        a   = DTC * (lam + 2.0f * mu) * inv_dx;
        cc  = DTC * mu  * inv_dx;
        dtr = (DTC / den) * inv_dx;
        float a1 = (float)(NPML - i);
        float a2 = (float)(i - (NZP - 1 - NPML));
        float dz = fmaxf(a1, a2); dz = fminf(fmaxf(dz, 0.0f), (float)NPML) / (float)NPML;
        float b1 = (float)(NPML - j);
        float b2 = (float)(j - (NXP - 1 - NPML));
        float dxs = fmaxf(b1, b2); dxs = fminf(fmaxf(dxs, 0.0f), (float)NPML) / (float)NPML;
        dmp = expf(-0.1f * (dz * dz + dxs * dxs));
    };

    const int sid  = ShotIds[s];
    const int srcx = NPML + 20 + sid * ((NX - 40) / NSHOTS);
    const float* stf = Stf + sid * NSTEPS;

    // ---------- compute cells (boundary rows FIRST); coeffs + field state in regs ----------
    unsigned enc[MAXC];
    float cdm[MAXC], cdt[MAXC], cA[MAXC], cC[MAXC];
    float rvx[MAXC], rvz[MAXC], rsxx[MAXC], rszz[MAXC], rsxz[MAXC];

    #pragma unroll
    for (int k = 0; k < MAXC; ++k) {
        int c  = tid + k * NCMP;
        int v  = isComp && (c < ncells);
        int cc2 = v ? c : 0;
        int r, j;
        if (cc2 < NXP)          { r = 2;         j = cc2; }
        else if (cc2 < 2 * NXP) { r = nrows + 1; j = cc2 - NXP; }
        else { int e = cc2 - 2 * NXP; int rr = e / NXP; r = 3 + rr; j = e - rr * NXP; }
        int i = z0 - 2 + r;

        int f = v ? F_VAL : 0;
        if (v && i == REC_Z && j >= NPML && j < NPML + NX) f |= F_REC;
        if (v && i == SRC_Z && j == srcx)                  f |= F_SRC;
        if (v && r == 2)          f |= F_TOP;
        if (v && r == nrows + 1)  f |= F_BOT;
        enc[k] = (unsigned)(r * SPITCH + j) | ((unsigned)f << 20);

        float dtr, dmp, a, cc;
        coef(i, j, dtr, dmp, a, cc);
        cdt[k] = dtr; cdm[k] = dmp; cA[k] = a; cC[k] = cc;
        rvx[k] = 0.0f; rvz[k] = 0.0f; rsxx[k] = 0.0f; rszz[k] = 0.0f; rsxz[k] = 0.0f;
    }

    // ---------- stress-halo recompute cells (compute threads only) ----------
    const bool topHr = (nb_lo >= 0 && tid < NXP);                  // sxz(z0-1) at j=tid
    const bool botHr = (nb_hi >= 0 && tid >= 464 && tid < 928);    // szz(z1)   at j=tid-464
    float hCt = 0.0f, hdampT = 0.0f;
    float hA = 0.0f, hCb = 0.0f, hdampB = 0.0f;
    bool  srcB = false;
    if (topHr) {
        float dtr, a;
        coef(z0 - 1, tid, dtr, hdampT, a, hCt);
    }
    if (botHr) {
        int j = tid - 464;
        float dtr;
        coef(z1, j, dtr, hdampB, hA, hCb);
        srcB = (z1 == SRC_Z && j == srcx);
    }

    __syncthreads();   // smem zero + setup done (block-local)

    double acc = 0.0;

    const int topSO = 1 * SPITCH;              // row z0-1
    const int botSO = (nrows + 2) * SPITCH;    // row z1

    // ---------------- time loop ----------------
    for (int t = 0; t < NSTEPS; ++t) {
        const int p = t & 1;
        float* __restrict__ vxg = g_vx[p][s];
        float* __restrict__ vzg = g_vz[p][s];

        // ---- velocity body: centers from registers, stress neighbors from smem ----
        auto vcell = [&](int k) {
            const int f = (int)(enc[k] >> 20);
            if (!(f & F_VAL)) return;
            const int so = (int)(enc[k] & 0xFFFFFu);
            float sxx_r = s_sxx[so + 1];
            float sxz_u = s_sxz[so - SPITCH];
            float sxz_l = s_sxz[so - 1];
            float szz_d = s_szz[so + SPITCH];
            float nvx = (rvx[k] + cdt[k] * ((sxx_r - rsxx[k]) + (rsxz[k] - sxz_u))) * cdm[k];
            float nvz = (rvz[k] + cdt[k] * ((rsxz[k] - sxz_l) + (szz_d - rszz[k]))) * cdm[k];
            rvx[k] = nvx;
            rvz[k] = nvz;
            s_vx[so] = nvx;
            s_vz[so] = nvz;
            if (f & (F_TOP | F_BOT)) {
                __stcg(&vxg[gbase + so], nvx);
                __stcg(&vzg[gbase + so], nvz);
            }
            if (f & F_REC) acc += (double)nvx * (double)nvx;
        };

        // ===== velocity phase =====
        if (isComp) vcell(0);                      // boundary rows z0, z1-1 first
        __syncthreads();                           // bar1: boundary V stores done
        ++q;
        if (tid == 0) st_release_u32(myflag, q);   // publish V(t) boundary

        if (isComp) {
            vcell(1); vcell(2);                    // interior compute (mattress)
        } else if (isTopImp) {
            // every lane acquire-polls (proper per-load ordering), then bulk import.
            // SAFE concurrently with vcell: vcell never reads s_vx/s_vz.
            wait_flag(&g_flags[nb_lo * 32], q);
            #pragma unroll 4
            for (int j = lane; j < NXP; j += 32) {
                s_vx[topSO + j] = __ldcg(&vxg[(z0 - 1) * NXPP + j]);
                s_vz[topSO + j] = __ldcg(&vzg[(z0 - 1) * NXPP + j]);
            }
        } else if (isBotImp) {
            wait_flag(&g_flags[nb_hi * 32], q);
            #pragma unroll 4
            for (int j = lane; j < NXP; j += 32) {
                s_vx[botSO + j] = __ldcg(&vxg[z1 * NXPP + j]);
                s_vz[botSO + j] = __ldcg(&vzg[z1 * NXPP + j]);
            }
        }
        __syncthreads();                           // bar2: all velocity (owned + halos) ready

        // ---- stress body: centers from registers, velocity neighbors from smem ----
        auto scell = [&](int k) {
            const int f = (int)(enc[k] >> 20);
            if (!(f & F_VAL)) return;
            const int so = (int)(enc[k] & 0xFFFFFu);
            float vx_l = s_vx[so - 1];
            float vx_d = s_vx[so + SPITCH];
            float vz_u = s_vz[so - SPITCH];
            float vz_r = s_vz[so + 1];
            float dx = rvx[k] - vx_l;
            float dz = rvz[k] - vz_u;
            float B = cA[k] - 2.0f * cC[k];
            float sxxn = (rsxx[k] + cA[k] * dx + B * dz) * cdm[k];
            float szzn = (rszz[k] + B * dx + cA[k] * dz) * cdm[k];
            float sxzn = (rsxz[k] + cC[k] * ((vx_d - rvx[k]) + (vz_r - rvz[k]))) * cdm[k];
            if (f & F_SRC) {
                float sv = stf[t] * DTC;
                sxxn += sv;
                szzn += sv;
            }
            rsxx[k] = sxxn; rszz[k] = szzn; rsxz[k] = sxzn;
            s_sxx[so] = sxxn;
            s_szz[so] = szzn;
            s_sxz[so] = sxzn;
        };

        // ===== stress phase + stress-halo recompute =====
        if (isComp) { scell(0); scell(1); scell(2); }

        if (topHr) {   // sxz(z0-1): bit-identical recompute of lo neighbor's row
            const int so = topSO + tid;
            float v = (s_sxz[so] + hCt * ((s_vx[so + SPITCH] - s_vx[so])
                                        + (s_vz[so + 1]      - s_vz[so]))) * hdampT;
            s_sxz[so] = v;
        }
        if (botHr) {   // szz(z1): same B = A - 2C derivation as owned cells
            const int j  = tid - 464;
            const int so = botSO + j;
            float dx = s_vx[so] - s_vx[so - 1];
            float dz = s_vz[so] - s_vz[so - SPITCH];
            float Bb = hA - 2.0f * hCb;
            float v = (s_szz[so] + Bb * dx + hA * dz) * hdampB;
            if (srcB) v += stf[t] * DTC;
            s_szz[so] = v;
        }
        __syncthreads();                           // bar3
    }

    // ---------------- deterministic reduction ----------------
    __shared__ double sh[NTHR];
    sh[tid] = acc;
    __syncthreads();
    for (int o = NTHR / 2; o > 0; o >>= 1) {
        if (tid < o) sh[tid] += sh[tid + o];
        __syncthreads();
    }

    __shared__ int is_last;
    if (tid == 0) {
        g_part[b] = sh[0];
        __threadfence();
        unsigned ticket = atomicAdd(&g_done, 1u);
        is_last = ((ticket + 1u) % NBLK == 0u) ? 1 : 0;
    }
    __syncthreads();

    if (is_last) {
        __threadfence();
        double a = 0.0;
        if (tid < NBLK) a = __ldcg(&g_part[tid]);
        sh[tid] = a;
        __syncthreads();
        for (int o = NTHR / 2; o > 0; o >>= 1) {
            if (tid < o) sh[tid] += sh[tid + o];
            __syncthreads();
        }
        if (tid == 0) out[0] = (float)(0.5 * sh[0]);
    }
}

// ---------------- launcher ----------------
extern "C" void kernel_launch(void* const* d_in, const int* in_sizes, int n_in,
                              void* d_out, int out_size)
{
    const float* Vp      = (const float*)d_in[0];
    const float* Vs      = (const float*)d_in[1];
    const float* Den     = (const float*)d_in[2];
    const float* Stf     = (const float*)d_in[3];
    const float* Mask    = (const float*)d_in[4];
    const int*   ShotIds = (const int*)  d_in[5];
    float*       out     = (float*)d_out;
    (void)in_sizes; (void)n_in; (void)out_size;

    static int smem_set = 0;
    if (!smem_set) {
        cudaFuncSetAttribute(fwi_persistent,
                             cudaFuncAttributeMaxDynamicSharedMemorySize, SMEM_DYN);
        smem_set = 1;
    }

    fwi_persistent<<<NBLK, NTHR, SMEM_DYN>>>(Vp, Vs, Den, Stf, Mask, ShotIds, out);
}

// round 16
// speedup vs baseline: 1.5147x; 1.5147x over previous
#include <cuda_runtime.h>

// ---------------- problem constants ----------------
#define NZ     300
#define NX     400
#define NPML   32
#define NZP    (NZ + 2*NPML)            // 364
#define NXP    (NX + 2*NPML)            // 464
#define NXPP   480                      // global row pitch (floats)
#define NSTEPS 200
#define NSHOTS 2
#define DXC    0.01f
#define DTC    0.001f
#define SRC_Z  (NPML + 2)               // 34
#define REC_Z  (NPML + 2)               // 34

#define FSZ (NZP * NXPP)

#define BLKS_PER_SHOT 74
#define NBLK   (NSHOTS * BLKS_PER_SHOT) // 148
#define NTHR   1024
#define MAXC   3

// smem tile: row r <-> global row z0-2+r
//   r=0 guard(0), r=1 = z0-1 (vx/vz imported, sxz recomputed),
//   r=2..nrows+1 owned, r=nrows+2 = z1 (vx/vz imported, szz recomputed)
#define SROWS  8
#define SPITCH 480
#define FTILE  (SROWS * SPITCH)
#define SMEM_DYN (5 * FTILE * 4)        // 76800 B

// enc = soff | flags<<20
#define F_VAL  1
#define F_REC  2
#define F_SRC  4
#define F_TOP  8     // r == 2        -> publish vx,vz to lo
#define F_BOT  16    // r == nrows+1  -> publish vx,vz to hi

// ---------------- device state (static, no allocs) ----------------
// Parity double-buffered velocity exchange. Overrun-proof: block A rewrites
// parity p only at step t+2; reaching its t+2 vcell(0) requires its bar1@t+1,
// which requires neighbor's flag q_{t+1}; the neighbor sets q_{t+1} only
// after its bar1@t+1, which follows its bar2@t, which follows its import of
// parity p at step t. So the read always completes before the overwrite.
__device__ float g_vx[2][NSHOTS][FSZ];
__device__ float g_vz[2][NSHOTS][FSZ];

__device__ unsigned g_flags[NBLK * 32];   // monotonic, 128B apart
__device__ double   g_part[NBLK];
__device__ unsigned g_done = 0u;

__device__ __forceinline__ void st_release_u32(unsigned* p, unsigned v)
{
    asm volatile("st.release.gpu.global.u32 [%0], %1;" :: "l"(p), "r"(v) : "memory");
}
__device__ __forceinline__ unsigned ld_acquire_u32(const unsigned* p)
{
    unsigned v;
    asm volatile("ld.acquire.gpu.global.u32 %0, [%1];" : "=r"(v) : "l"(p) : "memory");
    return v;
}
__device__ __forceinline__ void wait_flag(const unsigned* f, unsigned q)
{
    while ((int)(ld_acquire_u32(f) - q) < 0) { }
}

__global__ void __launch_bounds__(NTHR, 1)
fwi_persistent(const float* __restrict__ Vp,
               const float* __restrict__ Vs,
               const float* __restrict__ Den,
               const float* __restrict__ Stf,
               const float* __restrict__ Mask,
               const int*   __restrict__ ShotIds,
               float*       __restrict__ out)
{
    extern __shared__ float sm[];
    float* __restrict__ s_vx  = sm;
    float* __restrict__ s_vz  = sm + 1 * FTILE;
    float* __restrict__ s_sxx = sm + 2 * FTILE;
    float* __restrict__ s_szz = sm + 3 * FTILE;
    float* __restrict__ s_sxz = sm + 4 * FTILE;

    const int b   = blockIdx.x;
    const int s   = b / BLKS_PER_SHOT;
    const int kk  = b - s * BLKS_PER_SHOT;
    const int z0  = (kk * NZP) / BLKS_PER_SHOT;
    const int z1  = ((kk + 1) * NZP) / BLKS_PER_SHOT;
    const int nrows  = z1 - z0;
    const int ncells = nrows * NXP;
    const int tid = threadIdx.x;

    const int nb_lo = (kk > 0)                 ? b - 1 : -1;
    const int nb_hi = (kk < BLKS_PER_SHOT - 1) ? b + 1 : -1;

    const int gbase = (z0 - 2) * NXPP;     // global offset of smem row 0

    unsigned  q      = *(volatile unsigned*)&g_flags[b * 32];   // replay-safe base
    unsigned* myflag = &g_flags[b * 32];

    // ---------- zero smem tiles ----------
    for (int c = tid; c < 5 * FTILE; c += NTHR) sm[c] = 0.0f;

    // ---------- coefficient helper (A = dt*(lam+2mu)/dx, C = dt*mu/dx) ----------
    auto coef = [&](int i, int j, float& dtr, float& dmp, float& a, float& cc) {
        int ip = min(max(i - NPML, 0), NZ - 1);
        int jp = min(max(j - NPML, 0), NX - 1);
        float vp  = Vp [ip * NX + jp];
        float vs  = Vs [ip * NX + jp];
        float den = Den[ip * NX + jp];
        float m   = Mask[i * NXP + j];
        vp  = m * vp  + (1.0f - m) * vp;
        vs  = m * vs  + (1.0f - m) * vs;
        den = m * den + (1.0f - m) * den;
        float mu  = vs * vs * den * 1e-6f;
        float lam = (vp * vp - 2.0f * vs * vs) * den * 1e-6f;
        const float inv_dx = 1.0f / DXC;
        a   = DTC * (lam + 2.0f * mu) * inv_dx;
        cc  = DTC * mu  * inv_dx;
        dtr = (DTC / den) * inv_dx;
        float a1 = (float)(NPML - i);
        float a2 = (float)(i - (NZP - 1 - NPML));
        float dz = fmaxf(a1, a2); dz = fminf(fmaxf(dz, 0.0f), (float)NPML) / (float)NPML;
        float b1 = (float)(NPML - j);
        float b2 = (float)(j - (NXP - 1 - NPML));
        float dxs = fmaxf(b1, b2); dxs = fminf(fmaxf(dxs, 0.0f), (float)NPML) / (float)NPML;
        dmp = expf(-0.1f * (dz * dz + dxs * dxs));
    };

    const int sid  = ShotIds[s];
    const int srcx = NPML + 20 + sid * ((NX - 40) / NSHOTS);
    const float* stf = Stf + sid * NSTEPS;

    // ---------- per-thread cells (boundary rows FIRST); coeffs + field state in regs ----------
    unsigned enc[MAXC];
    float cdm[MAXC], cdt[MAXC], cA[MAXC], cC[MAXC];
    float rvx[MAXC], rvz[MAXC], rsxx[MAXC], rszz[MAXC], rsxz[MAXC];

    #pragma unroll
    for (int k = 0; k < MAXC; ++k) {
        int c  = tid + k * NTHR;
        int v  = (c < ncells);
        int cc2 = v ? c : 0;
        int r, j;
        if (cc2 < NXP)          { r = 2;         j = cc2; }
        else if (cc2 < 2 * NXP) { r = nrows + 1; j = cc2 - NXP; }
        else { int e = cc2 - 2 * NXP; int rr = e / NXP; r = 3 + rr; j = e - rr * NXP; }
        int i = z0 - 2 + r;

        int f = v ? F_VAL : 0;
        if (v && i == REC_Z && j >= NPML && j < NPML + NX) f |= F_REC;
        if (v && i == SRC_Z && j == srcx)                  f |= F_SRC;
        if (v && r == 2)          f |= F_TOP;
        if (v && r == nrows + 1)  f |= F_BOT;
        enc[k] = (unsigned)(r * SPITCH + j) | ((unsigned)f << 20);

        float dtr, dmp, a, cc;
        coef(i, j, dtr, dmp, a, cc);
        cdt[k] = dtr; cdm[k] = dmp; cA[k] = a; cC[k] = cc;
        rvx[k] = 0.0f; rvz[k] = 0.0f; rsxx[k] = 0.0f; rszz[k] = 0.0f; rsxz[k] = 0.0f;
    }

    // ---------- stress-halo recompute cells ----------
    const bool topH = (nb_lo >= 0 && tid < NXP);
    const bool botH = (nb_hi >= 0 && tid >= 512 && tid < 512 + NXP);
    float hCt = 0.0f, hdampT = 0.0f;           // top: mu coeff + damp (sxz)
    float hA = 0.0f, hCb = 0.0f, hdampB = 0.0f;// bottom: A, C + damp (szz)
    bool  srcB = false;
    if (topH) {
        float dtr, a;
        coef(z0 - 1, tid, dtr, hdampT, a, hCt);
    }
    if (botH) {
        int j = tid - 512;
        float dtr;
        coef(z1, j, dtr, hdampB, hA, hCb);
        srcB = (z1 == SRC_Z && j == srcx);
    }

    __syncthreads();   // smem zero + setup done (block-local)

    double acc = 0.0;

    const int topSO = 1 * SPITCH;              // row z0-1
    const int botSO = (nrows + 2) * SPITCH;    // row z1

    // ---------------- time loop ----------------
    for (int t = 0; t < NSTEPS; ++t) {
        const int p = t & 1;
        float* __restrict__ vxg = g_vx[p][s];
        float* __restrict__ vzg = g_vz[p][s];

        // ---- velocity body: centers from registers, stress neighbors from smem ----
        auto vcell = [&](int k) {
            const int f = (int)(enc[k] >> 20);
            if (!(f & F_VAL)) return;
            const int so = (int)(enc[k] & 0xFFFFFu);
            float sxx_r = s_sxx[so + 1];
            float sxz_u = s_sxz[so - SPITCH];
            float sxz_l = s_sxz[so - 1];
            float szz_d = s_szz[so + SPITCH];
            float nvx = (rvx[k] + cdt[k] * ((sxx_r - rsxx[k]) + (rsxz[k] - sxz_u))) * cdm[k];
            float nvz = (rvz[k] + cdt[k] * ((rsxz[k] - sxz_l) + (szz_d - rszz[k]))) * cdm[k];
            rvx[k] = nvx;
            rvz[k] = nvz;
            s_vx[so] = nvx;
            s_vz[so] = nvz;
            if (f & (F_TOP | F_BOT)) {
                __stcg(&vxg[gbase + so], nvx);
                __stcg(&vzg[gbase + so], nvz);
            }
            if (f & F_REC) acc += (double)nvx * (double)nvx;
        };

        // ===== velocity phase =====
        vcell(0);                                  // boundary rows z0, z1-1 first
        __syncthreads();                           // bar1
        ++q;
        if (tid == 0) st_release_u32(myflag, q);   // publish V(t) boundary

        vcell(1);                                  // mattress part 1 (~flag propagates)

        // poll late (flag almost surely set -> ~1 iteration, no line contention),
        // issue halo loads, hide their latency behind mattress part 2.
        float hvx = 0.0f, hvz = 0.0f;
        if (topH) {
            wait_flag(&g_flags[nb_lo * 32], q);
            hvx = __ldcg(&vxg[(z0 - 1) * NXPP + tid]);
            hvz = __ldcg(&vzg[(z0 - 1) * NXPP + tid]);
        }
        if (botH) {
            int j = tid - 512;
            wait_flag(&g_flags[nb_hi * 32], q);
            hvx = __ldcg(&vxg[z1 * NXPP + j]);
            hvz = __ldcg(&vzg[z1 * NXPP + j]);
        }

        vcell(2);                                  // mattress part 2 (hides ldcg)

        if (topH) { s_vx[topSO + tid] = hvx; s_vz[topSO + tid] = hvz; }
        if (botH) { int j = tid - 512; s_vx[botSO + j] = hvx; s_vz[botSO + j] = hvz; }
        __syncthreads();                           // bar2: all velocity (owned + halos) ready

        // ---- stress body: centers from registers, velocity neighbors from smem ----
        auto scell = [&](int k) {
            const int f = (int)(enc[k] >> 20);
            if (!(f & F_VAL)) return;
            const int so = (int)(enc[k] & 0xFFFFFu);
            float vx_l = s_vx[so - 1];
            float vx_d = s_vx[so + SPITCH];
            float vz_u = s_vz[so - SPITCH];
            float vz_r = s_vz[so + 1];
            float dx = rvx[k] - vx_l;
            float dz = rvz[k] - vz_u;
            float B = cA[k] - 2.0f * cC[k];
            float sxxn = (rsxx[k] + cA[k] * dx + B * dz) * cdm[k];
            float szzn = (rszz[k] + B * dx + cA[k] * dz) * cdm[k];
            float sxzn = (rsxz[k] + cC[k] * ((vx_d - rvx[k]) + (vz_r - rvz[k]))) * cdm[k];
            if (f & F_SRC) {
                float sv = stf[t] * DTC;
                sxxn += sv;
                szzn += sv;
            }
            rsxx[k] = sxxn; rszz[k] = szzn; rsxz[k] = sxzn;
            s_sxx[so] = sxxn;
            s_szz[so] = szzn;
            s_sxz[so] = sxzn;
        };

        // ===== stress phase + stress-halo recompute =====
        scell(0); scell(1); scell(2);

        if (topH) {   // sxz(z0-1): bit-identical recompute of lo neighbor's row
            const int so = topSO + tid;
            float v = (s_sxz[so] + hCt * ((s_vx[so + SPITCH] - s_vx[so])
                                        + (s_vz[so + 1]      - s_vz[so]))) * hdampT;
            s_sxz[so] = v;
        }
        if (botH) {   // szz(z1): same B = A - 2C derivation as owned cells
            const int j  = tid - 512;
            const int so = botSO + j;
            float dx = s_vx[so] - s_vx[so - 1];
            float dz = s_vz[so] - s_vz[so - SPITCH];
            float Bb = hA - 2.0f * hCb;
            float v = (s_szz[so] + Bb * dx + hA * dz) * hdampB;
            if (srcB) v += stf[t] * DTC;
            s_szz[so] = v;
        }
        __syncthreads();                           // bar3
    }

    // ---------------- deterministic reduction ----------------
    __shared__ double sh[NTHR];
    sh[tid] = acc;
    __syncthreads();
    for (int o = NTHR / 2; o > 0; o >>= 1) {
        if (tid < o) sh[tid] += sh[tid + o];
        __syncthreads();
    }

    __shared__ int is_last;
    if (tid == 0) {
        g_part[b] = sh[0];
        __threadfence();
        unsigned ticket = atomicAdd(&g_done, 1u);
        is_last = ((ticket + 1u) % NBLK == 0u) ? 1 : 0;
    }
    __syncthreads();

    if (is_last) {
        __threadfence();
        double a = 0.0;
        if (tid < NBLK) a = __ldcg(&g_part[tid]);
        sh[tid] = a;
        __syncthreads();
        for (int o = NTHR / 2; o > 0; o >>= 1) {
            if (tid < o) sh[tid] += sh[tid + o];
            __syncthreads();
        }
        if (tid == 0) out[0] = (float)(0.5 * sh[0]);
    }
}

// ---------------- launcher ----------------
extern "C" void kernel_launch(void* const* d_in, const int* in_sizes, int n_in,
                              void* d_out, int out_size)
{
    const float* Vp      = (const float*)d_in[0];
    const float* Vs      = (const float*)d_in[1];
    const float* Den     = (const float*)d_in[2];
    const float* Stf     = (const float*)d_in[3];
    const float* Mask    = (const float*)d_in[4];
    const int*   ShotIds = (const int*)  d_in[5];
    float*       out     = (float*)d_out;
    (void)in_sizes; (void)n_in; (void)out_size;

    static int smem_set = 0;
    if (!smem_set) {
        cudaFuncSetAttribute(fwi_persistent,
                             cudaFuncAttributeMaxDynamicSharedMemorySize, SMEM_DYN);
        smem_set = 1;
    }

    fwi_persistent<<<NBLK, NTHR, SMEM_DYN>>>(Vp, Vs, Den, Stf, Mask, ShotIds, out);
}